// round 6
// baseline (speedup 1.0000x reference)
#include <cuda_runtime.h>

#define D        64
#define KCODES   1024
#define BR       128
#define BK       128
#define NTHREADS 256
#define PAD      65   // 64 + 1 pad -> conflict-free strided LDS

// scratch (no allocation allowed): full codebook norms + loss accumulator
__device__ float g_e[KCODES];
__device__ float g_loss;

// smem layout (dynamic):
//   sX   [BR*PAD] floats
//   sE   [BK*PAD] floats
//   sH   [BK]     floats   (enorm tile)
//   sXn  [BR]     floats   (row norms, bit-matched sequential order)
//   sIdx [BR]     ints
//   sRed [8]      floats
#define SMEM_BYTES ((BR*PAD + BK*PAD + BK + BR)*4 + BR*4 + 8*4)

// enorm_k = sum_d fl(e*e), sequential order d=0..63, mul/add separately rounded
// (replicates XLA eager elementwise-square + unvectorized reduce)
__global__ void vq_prep(const float* __restrict__ cb) {
    int k = blockIdx.x * blockDim.x + threadIdx.x;
    if (k == 0) g_loss = 0.0f;
    if (k < KCODES) {
        const float* p = cb + k * D;
        float s = 0.0f;
        #pragma unroll
        for (int i = 0; i < D; ++i)
            s = __fadd_rn(s, __fmul_rn(p[i], p[i]));
        g_e[k] = s;
    }
}

extern __shared__ float smem_dyn[];

__global__ __launch_bounds__(NTHREADS, 2) void vq_main(
    const float* __restrict__ x, const float* __restrict__ cb,
    float* __restrict__ out, int nrows)
{
    float* sX   = smem_dyn;                 // BR*PAD
    float* sE   = sX + BR * PAD;            // BK*PAD
    float* sH   = sE + BK * PAD;            // BK
    float* sXn  = sH + BK;                  // BR
    int*   sIdx = (int*)(sXn + BR);         // BR
    float* sRed = (float*)(sIdx + BR);      // 8

    const int tid = threadIdx.x;
    const int tx  = tid & 15;               // code group
    const int ty  = tid >> 4;               // row group
    const int rowbase = blockIdx.x * BR;
    const int rows_here = min(BR, nrows - rowbase);

    // ---- load X tile [BR x D] (float4 global -> padded smem) ----
    {
        const float4* gx = (const float4*)(x + (size_t)rowbase * D);
        for (int e = tid; e < BR * D / 4; e += NTHREADS) {
            int r = e >> 4;             // 16 float4 per row
            int d = (e & 15) << 2;
            float4 v;
            if (r < rows_here) v = gx[e];
            else               v = make_float4(0.f, 0.f, 0.f, 0.f);
            float* p = sX + r * PAD + d;
            p[0] = v.x; p[1] = v.y; p[2] = v.z; p[3] = v.w;
        }
    }
    __syncthreads();

    // ---- row norms, bit-matched: sequential d=0..63, rounded mul then add ----
    if (tid < BR) {
        const float* p = sX + tid * PAD;
        float s = 0.0f;
        #pragma unroll
        for (int i = 0; i < D; ++i)
            s = __fadd_rn(s, __fmul_rn(p[i], p[i]));
        sXn[tid] = s;
    }

    float bestv[8];
    int   besti[8];
    #pragma unroll
    for (int i = 0; i < 8; ++i) { bestv[i] = 3.4e38f; besti[i] = 0; }

    // ---- K loop over codebook tiles ----
    for (int t = 0; t < KCODES / BK; ++t) {
        __syncthreads();
        {
            const float4* ge = (const float4*)(cb + (size_t)t * BK * D);
            for (int e = tid; e < BK * D / 4; e += NTHREADS) {
                float4 v = ge[e];
                int r = e >> 4;
                int d = (e & 15) << 2;
                float* p = sE + r * PAD + d;
                p[0] = v.x; p[1] = v.y; p[2] = v.z; p[3] = v.w;
            }
            if (tid < BK) sH[tid] = g_e[t * BK + tid];
        }
        __syncthreads();

        // dot accumulation: ascending-d FFMA chain, one accumulator per
        // (row, code) pair -> bitwise-matches Eigen gebp's k-chain
        float acc[8][8];
        #pragma unroll
        for (int i = 0; i < 8; ++i)
            #pragma unroll
            for (int j = 0; j < 8; ++j) acc[i][j] = 0.0f;

        #pragma unroll 4
        for (int d = 0; d < D; ++d) {
            float xv[8], ev[8];
            #pragma unroll
            for (int i = 0; i < 8; ++i) xv[i] = sX[(ty + 16 * i) * PAD + d];
            #pragma unroll
            for (int j = 0; j < 8; ++j) ev[j] = sE[(tx + 16 * j) * PAD + d];
            #pragma unroll
            for (int i = 0; i < 8; ++i)
                #pragma unroll
                for (int j = 0; j < 8; ++j) acc[i][j] += xv[i] * ev[j];
        }

        // fold: dist = fl(fl(xnorm + enorm) - fl(2*mm)), exactly like the
        // reference's broadcast add then subtract. Ascending code order +
        // strict '<' keeps the lowest index on quantized ties.
        #pragma unroll
        for (int j = 0; j < 8; ++j) {
            int   code = t * BK + tx + 16 * j;
            float en   = sH[tx + 16 * j];
            #pragma unroll
            for (int i = 0; i < 8; ++i) {
                float pre  = __fadd_rn(sXn[ty + 16 * i], en);
                float dist = __fsub_rn(pre, __fmul_rn(2.0f, acc[i][j]));
                if (dist < bestv[i]) { bestv[i] = dist; besti[i] = code; }
            }
        }
    }

    // ---- reduce argmin across the 16 code-group lanes (xor over tx bits) ----
    #pragma unroll
    for (int i = 0; i < 8; ++i) {
        #pragma unroll
        for (int m = 1; m < 16; m <<= 1) {
            float ov = __shfl_xor_sync(0xffffffffu, bestv[i], m);
            int   oi = __shfl_xor_sync(0xffffffffu, besti[i], m);
            if (ov < bestv[i] || (ov == bestv[i] && oi < besti[i])) {
                bestv[i] = ov; besti[i] = oi;
            }
        }
        if (tx == 0) sIdx[ty + 16 * i] = besti[i];
    }
    __syncthreads();

    // ---- epilogue: gather codewords, write output, accumulate loss ----
    float lsum = 0.0f;
    for (int e = tid; e < BR * D; e += NTHREADS) {
        int r = e >> 6;
        int d = e & 63;
        if (r < rows_here) {
            int   k  = sIdx[r];
            float q  = __ldg(cb + (size_t)k * D + d);
            float xv = sX[r * PAD + d];
            out[(size_t)(rowbase + r) * D + d] = q;
            float df = q - xv;
            lsum += df * df;
        }
    }
    #pragma unroll
    for (int m = 16; m >= 1; m >>= 1)
        lsum += __shfl_xor_sync(0xffffffffu, lsum, m);
    if ((tid & 31) == 0) sRed[tid >> 5] = lsum;
    __syncthreads();
    if (tid < 8) {
        float v = sRed[tid];
        #pragma unroll
        for (int m = 4; m >= 1; m >>= 1)
            v += __shfl_xor_sync(0x000000ffu, v, m);
        if (tid == 0) atomicAdd(&g_loss, v);
    }
}

__global__ void vq_finish(float* out, int pos, float inv_n) {
    // vq_loss = codebook_loss + 0.25*commitment_loss; both equal mean((q-x)^2)
    out[pos] = 1.25f * g_loss * inv_n;
}

extern "C" void kernel_launch(void* const* d_in, const int* in_sizes, int n_in,
                              void* d_out, int out_size) {
    const float* x  = (const float*)d_in[0];
    const float* cb = (const float*)d_in[1];
    float* out = (float*)d_out;

    const int nrows = in_sizes[0] / D;              // 65536
    const int nblocks = (nrows + BR - 1) / BR;      // 512

    cudaFuncSetAttribute(vq_main, cudaFuncAttributeMaxDynamicSharedMemorySize,
                         SMEM_BYTES);

    vq_prep<<<(KCODES + 127) / 128, 128>>>(cb);
    vq_main<<<nblocks, NTHREADS, SMEM_BYTES>>>(x, cb, out, nrows);
    vq_finish<<<1, 1>>>(out, out_size - 1, 1.0f / (float)((size_t)nrows * D));
}

// round 7
// speedup vs baseline: 1.0184x; 1.0184x over previous
#include <cuda_runtime.h>

#define D        64
#define KCODES   1024
#define BR       128
#define BK       128
#define NTHREADS 256
#define PAD      65    // sX row pad -> conflict-free strided LDS
#define EPAD     130   // sEt row stride in floats (even -> LDS.64 aligned)

typedef unsigned long long ull;

// scratch (no allocation allowed): codebook norms + loss accumulator
__device__ float g_e[KCODES];
__device__ float g_loss;

// smem layout (dynamic):
//   sX   [BR*PAD]  floats   (row-major X tile)
//   sEt  [D*EPAD]  floats   (TRANSPOSED codebook tile: [d][code])
//   sH   [BK]      floats   (enorm tile)
//   sXn  [BR]      floats   (row norms, bit-matched sequential order)
//   sIdx [BR]      ints
//   sRed [8]       floats
#define SMEM_BYTES ((BR*PAD + D*EPAD + BK + BR)*4 + BR*4 + 8*4)

__device__ __forceinline__ void ffma2(ull& d, ull a, ull b) {
    asm("fma.rn.f32x2 %0, %1, %2, %0;" : "+l"(d) : "l"(a), "l"(b));
}
__device__ __forceinline__ ull pack2(float lo, float hi) {
    ull r;
    asm("mov.b64 %0, {%1, %2};" : "=l"(r) : "f"(lo), "f"(hi));
    return r;
}
__device__ __forceinline__ void unpack2(ull v, float& lo, float& hi) {
    asm("mov.b64 {%0, %1}, %2;" : "=f"(lo), "=f"(hi) : "l"(v));
}

// enorm_k = sum_d fl(e*e), sequential d=0..63, mul/add separately rounded
// (replicates the reference's elementwise-square + sequential reduce)
__global__ void vq_prep(const float* __restrict__ cb) {
    int k = blockIdx.x * blockDim.x + threadIdx.x;
    if (k == 0) g_loss = 0.0f;
    if (k < KCODES) {
        const float* p = cb + k * D;
        float s = 0.0f;
        #pragma unroll
        for (int i = 0; i < D; ++i)
            s = __fadd_rn(s, __fmul_rn(p[i], p[i]));
        g_e[k] = s;
    }
}

extern __shared__ float smem_dyn[];

__global__ __launch_bounds__(NTHREADS, 2) void vq_main(
    const float* __restrict__ x, const float* __restrict__ cb,
    float* __restrict__ out, int nrows)
{
    float* sX   = smem_dyn;                 // BR*PAD
    float* sEt  = sX + BR * PAD;            // D*EPAD
    float* sH   = sEt + D * EPAD;           // BK
    float* sXn  = sH + BK;                  // BR
    int*   sIdx = (int*)(sXn + BR);         // BR
    float* sRed = (float*)(sIdx + BR);      // 8

    const int tid = threadIdx.x;
    const int tx  = tid & 15;               // code-pair group
    const int ty  = tid >> 4;               // row group
    const int rowbase = blockIdx.x * BR;
    const int rows_here = min(BR, nrows - rowbase);

    // ---- load X tile [BR x D] (float4 global -> padded smem) ----
    {
        const float4* gx = (const float4*)(x + (size_t)rowbase * D);
        for (int e = tid; e < BR * D / 4; e += NTHREADS) {
            int r = e >> 4;             // 16 float4 per row
            int d = (e & 15) << 2;
            float4 v;
            if (r < rows_here) v = gx[e];
            else               v = make_float4(0.f, 0.f, 0.f, 0.f);
            float* p = sX + r * PAD + d;
            p[0] = v.x; p[1] = v.y; p[2] = v.z; p[3] = v.w;
        }
    }
    __syncthreads();

    // ---- row norms, bit-matched: sequential d=0..63, rounded mul then add ----
    if (tid < BR) {
        const float* p = sX + tid * PAD;
        float s = 0.0f;
        #pragma unroll
        for (int i = 0; i < D; ++i)
            s = __fadd_rn(s, __fmul_rn(p[i], p[i]));
        sXn[tid] = s;
    }

    float bestv[8];
    int   besti[8];
    #pragma unroll
    for (int i = 0; i < 8; ++i) { bestv[i] = 3.4e38f; besti[i] = 0; }

    // ---- K loop over codebook tiles ----
    for (int t = 0; t < KCODES / BK; ++t) {
        __syncthreads();
        {
            // load tile coalesced, write TRANSPOSED: sEt[d][c]
            const float4* ge = (const float4*)(cb + (size_t)t * BK * D);
            for (int e = tid; e < BK * D / 4; e += NTHREADS) {
                float4 v = ge[e];
                int c = e >> 4;             // code 0..127
                int d = (e & 15) << 2;
                sEt[(d + 0) * EPAD + c] = v.x;
                sEt[(d + 1) * EPAD + c] = v.y;
                sEt[(d + 2) * EPAD + c] = v.z;
                sEt[(d + 3) * EPAD + c] = v.w;
            }
            if (tid < BK) sH[tid] = g_e[t * BK + tid];
        }
        __syncthreads();

        // packed-f32x2 dot accumulation: each 64-bit acc holds codes
        // (2*tx+32*jp, +1) for one row. Per-lane FFMA2 is IEEE-rn fp32 FMA,
        // ascending-d single-accumulator chain -> bitwise-matches the
        // reference GEMM's per-element k-chain.
        ull acc2[8][4];
        #pragma unroll
        for (int i = 0; i < 8; ++i)
            #pragma unroll
            for (int jp = 0; jp < 4; ++jp) acc2[i][jp] = 0ull;

        #pragma unroll 4
        for (int d = 0; d < D; ++d) {
            ull ev2[4], xv2[8];
            const ull* pe = (const ull*)(sEt + EPAD * d);
            #pragma unroll
            for (int jp = 0; jp < 4; ++jp) ev2[jp] = pe[tx + 16 * jp];
            #pragma unroll
            for (int i = 0; i < 8; ++i) {
                float v = sX[(ty + 16 * i) * PAD + d];
                xv2[i] = pack2(v, v);
            }
            #pragma unroll
            for (int i = 0; i < 8; ++i)
                #pragma unroll
                for (int jp = 0; jp < 4; ++jp)
                    ffma2(acc2[i][jp], xv2[i], ev2[jp]);
        }

        // fold: dist = fl(fl(xnorm + enorm) - fl(2*mm)), even code before odd,
        // ascending jp; strict '<' keeps the lowest index on quantized ties.
        #pragma unroll
        for (int jp = 0; jp < 4; ++jp) {
            int   cb0  = 2 * tx + 32 * jp;
            float en0  = sH[cb0];
            float en1  = sH[cb0 + 1];
            int   code = t * BK + cb0;
            #pragma unroll
            for (int i = 0; i < 8; ++i) {
                float m0, m1;
                unpack2(acc2[i][jp], m0, m1);
                float xn = sXn[ty + 16 * i];
                float d0 = __fsub_rn(__fadd_rn(xn, en0), __fmul_rn(2.0f, m0));
                if (d0 < bestv[i]) { bestv[i] = d0; besti[i] = code; }
                float d1 = __fsub_rn(__fadd_rn(xn, en1), __fmul_rn(2.0f, m1));
                if (d1 < bestv[i]) { bestv[i] = d1; besti[i] = code + 1; }
            }
        }
    }

    // ---- reduce argmin across the 16 code-group lanes (xor over tx bits) ----
    #pragma unroll
    for (int i = 0; i < 8; ++i) {
        #pragma unroll
        for (int m = 1; m < 16; m <<= 1) {
            float ov = __shfl_xor_sync(0xffffffffu, bestv[i], m);
            int   oi = __shfl_xor_sync(0xffffffffu, besti[i], m);
            if (ov < bestv[i] || (ov == bestv[i] && oi < besti[i])) {
                bestv[i] = ov; besti[i] = oi;
            }
        }
        if (tx == 0) sIdx[ty + 16 * i] = besti[i];
    }
    __syncthreads();

    // ---- epilogue: gather codewords, write output, accumulate loss ----
    float lsum = 0.0f;
    for (int e = tid; e < BR * D; e += NTHREADS) {
        int r = e >> 6;
        int d = e & 63;
        if (r < rows_here) {
            int   k  = sIdx[r];
            float q  = __ldg(cb + (size_t)k * D + d);
            float xv = sX[r * PAD + d];
            out[(size_t)(rowbase + r) * D + d] = q;
            float df = q - xv;
            lsum += df * df;
        }
    }
    #pragma unroll
    for (int m = 16; m >= 1; m >>= 1)
        lsum += __shfl_xor_sync(0xffffffffu, lsum, m);
    if ((tid & 31) == 0) sRed[tid >> 5] = lsum;
    __syncthreads();
    if (tid < 8) {
        float v = sRed[tid];
        #pragma unroll
        for (int m = 4; m >= 1; m >>= 1)
            v += __shfl_xor_sync(0x000000ffu, v, m);
        if (tid == 0) atomicAdd(&g_loss, v);
    }
}

__global__ void vq_finish(float* out, int pos, float inv_n) {
    // vq_loss = codebook_loss + 0.25*commitment_loss; both equal mean((q-x)^2)
    out[pos] = 1.25f * g_loss * inv_n;
}

extern "C" void kernel_launch(void* const* d_in, const int* in_sizes, int n_in,
                              void* d_out, int out_size) {
    const float* x  = (const float*)d_in[0];
    const float* cb = (const float*)d_in[1];
    float* out = (float*)d_out;

    const int nrows = in_sizes[0] / D;              // 65536
    const int nblocks = (nrows + BR - 1) / BR;      // 512

    cudaFuncSetAttribute(vq_main, cudaFuncAttributeMaxDynamicSharedMemorySize,
                         SMEM_BYTES);

    vq_prep<<<(KCODES + 127) / 128, 128>>>(cb);
    vq_main<<<nblocks, NTHREADS, SMEM_BYTES>>>(x, cb, out, nrows);
    vq_finish<<<1, 1>>>(out, out_size - 1, 1.0f / (float)((size_t)nrows * D));
}